// round 2
// baseline (speedup 1.0000x reference)
#include <cuda_runtime.h>
#include <cstdint>

// FrozenBNBEmbedding: out[t, d] = code[ weight[input[t], d] ] * absmax[input[t]]
// DIM == BLOCK == 4096, so the per-block absmax index equals the vocab row index.
//
// Inputs (metadata order):
//   d_in[0] = input  : int32 [4, 2048]          (8192 token ids)
//   d_in[1] = weight : int32 [50400, 4096]      (int8 codes stored as int32)
//   d_in[2] = absmax : float32 [50400]          (per-row scale)
//   d_in[3] = code   : float32 [256]            (LUT)
//   d_out   = float32 [4, 2048, 4096]
//
// Round-2: bank-replicated LUT (conflict-free LDS), 8 tokens/CTA to amortize
// LUT init, explicit 4x LDG.128 batching per token, streaming stores.

#define DIM      4096
#define NTOKENS  8192
#define THREADS  256
#define NWARPS   (THREADS / 32)
#define T_PER_CTA 8
#define NCTAS    (NTOKENS / T_PER_CTA)

__global__ __launch_bounds__(THREADS)
void bnb_embed_kernel(const int* __restrict__ input,
                      const int* __restrict__ weight,
                      const float* __restrict__ absmax,
                      const float* __restrict__ code,
                      float* __restrict__ out)
{
    // Bank-replicated LUT: copy for each of the 32 banks.
    // Entry layout: s_lut[idx * 32 + lane]  -> bank == lane, conflict-free.
    __shared__ float s_lut[256 * 32];

    const int lane = threadIdx.x & 31;
    const int warp = threadIdx.x >> 5;

    #pragma unroll
    for (int idx = warp; idx < 256; idx += NWARPS) {
        const float c = __ldg(&code[idx]);      // L1/L2-resident, broadcast per warp
        s_lut[idx * 32 + lane] = c;             // contiguous 128B per warp, 1 wavefront
    }
    __syncthreads();

    const float* __restrict__ lut = s_lut + lane;   // index with (idx << 5)

    const int tbase = blockIdx.x * T_PER_CTA;

    #pragma unroll 1
    for (int tt = 0; tt < T_PER_CTA; tt++) {
        const int t   = tbase + tt;
        const int tok = __ldg(&input[t]);
        const float scale = __ldg(&absmax[tok]);

        const int4* __restrict__ wrow =
            reinterpret_cast<const int4*>(weight + (size_t)tok * DIM);
        float4* __restrict__ orow =
            reinterpret_cast<float4*>(out + (size_t)t * DIM);

        const int i = threadIdx.x;

        // Front-batch all four 16B loads: MLP=4 per thread.
        int4 q0 = wrow[i];
        int4 q1 = wrow[i + 256];
        int4 q2 = wrow[i + 512];
        int4 q3 = wrow[i + 768];

        float4 o0, o1, o2, o3;
        o0.x = lut[(q0.x & 255) << 5] * scale;
        o0.y = lut[(q0.y & 255) << 5] * scale;
        o0.z = lut[(q0.z & 255) << 5] * scale;
        o0.w = lut[(q0.w & 255) << 5] * scale;

        o1.x = lut[(q1.x & 255) << 5] * scale;
        o1.y = lut[(q1.y & 255) << 5] * scale;
        o1.z = lut[(q1.z & 255) << 5] * scale;
        o1.w = lut[(q1.w & 255) << 5] * scale;

        o2.x = lut[(q2.x & 255) << 5] * scale;
        o2.y = lut[(q2.y & 255) << 5] * scale;
        o2.z = lut[(q2.z & 255) << 5] * scale;
        o2.w = lut[(q2.w & 255) << 5] * scale;

        o3.x = lut[(q3.x & 255) << 5] * scale;
        o3.y = lut[(q3.y & 255) << 5] * scale;
        o3.z = lut[(q3.z & 255) << 5] * scale;
        o3.w = lut[(q3.w & 255) << 5] * scale;

        // Write-once output: streaming store hint.
        __stcs(&orow[i],       o0);
        __stcs(&orow[i + 256], o1);
        __stcs(&orow[i + 512], o2);
        __stcs(&orow[i + 768], o3);
    }
}

extern "C" void kernel_launch(void* const* d_in, const int* in_sizes, int n_in,
                              void* d_out, int out_size)
{
    const int*   input  = (const int*)  d_in[0];
    const int*   weight = (const int*)  d_in[1];
    const float* absmax = (const float*)d_in[2];
    const float* code   = (const float*)d_in[3];
    float*       out    = (float*)d_out;

    bnb_embed_kernel<<<NCTAS, THREADS>>>(input, weight, absmax, code, out);
}

// round 3
// speedup vs baseline: 1.0535x; 1.0535x over previous
#include <cuda_runtime.h>
#include <cstdint>

// FrozenBNBEmbedding: out[t, d] = code[ weight[input[t], d] ] * absmax[input[t]]
// DIM == BLOCK == 4096 -> absmax index == vocab row index.
//
// Inputs (metadata order):
//   d_in[0] = input  : int32 [4, 2048]       (8192 token ids)
//   d_in[1] = weight : int32 [50400, 4096]   (int8 codes as int32)
//   d_in[2] = absmax : float32 [50400]
//   d_in[3] = code   : float32 [256]
//   d_out   = float32 [4, 2048, 4096]
//
// Round-3: conflict-free 32-way replicated LUT (32KB) + 7 CTAs/SM
// (launch_bounds), grid=2048 (4 tok/CTA, 2 balanced waves), batched
// LDG.128 with token-id prefetch, immediate compute+store to cap regs.

#define DIM       4096
#define NTOKENS   8192
#define THREADS   256
#define NWARPS    (THREADS / 32)
#define T_PER_CTA 4
#define NCTAS     (NTOKENS / T_PER_CTA)

__global__ __launch_bounds__(THREADS, 7)
void bnb_embed_kernel(const int* __restrict__ input,
                      const int* __restrict__ weight,
                      const float* __restrict__ absmax,
                      const float* __restrict__ code,
                      float* __restrict__ out)
{
    // 32-way bank-replicated LUT: s_lut[idx*32 + lane] -> bank == lane.
    __shared__ float s_lut[256 * 32];

    const int lane = threadIdx.x & 31;
    const int warp = threadIdx.x >> 5;

    #pragma unroll
    for (int idx = warp; idx < 256; idx += NWARPS) {
        const float c = __ldg(&code[idx]);   // warp-uniform, L1 hit after first
        s_lut[idx * 32 + lane] = c;          // 128B contiguous per warp
    }
    __syncthreads();

    const float* __restrict__ lut = s_lut + lane;  // index with (byte << 5)

    const int tbase = blockIdx.x * T_PER_CTA;
    const int i = threadIdx.x;

    // Prefetch token ids: breaks the input[t] -> row-pointer chase out of the loop.
    int toks[T_PER_CTA];
    #pragma unroll
    for (int tt = 0; tt < T_PER_CTA; tt++)
        toks[tt] = __ldg(&input[tbase + tt]);

    #pragma unroll 1
    for (int tt = 0; tt < T_PER_CTA; tt++) {
        const int tok = toks[tt];
        const float scale = __ldg(&absmax[tok]);

        const int4* __restrict__ wrow =
            reinterpret_cast<const int4*>(weight + (size_t)tok * DIM);
        float4* __restrict__ orow =
            reinterpret_cast<float4*>(out + (size_t)(tbase + tt) * DIM);

        // Front-batch all four 16B loads (MLP=4 per thread).
        int4 q0 = wrow[i];
        int4 q1 = wrow[i + 256];
        int4 q2 = wrow[i + 512];
        int4 q3 = wrow[i + 768];

        // Compute + store each vector immediately (keeps live regs low;
        // stores are fire-and-forget).
        float4 o;
        o.x = lut[(q0.x & 255) << 5] * scale;
        o.y = lut[(q0.y & 255) << 5] * scale;
        o.z = lut[(q0.z & 255) << 5] * scale;
        o.w = lut[(q0.w & 255) << 5] * scale;
        orow[i] = o;

        o.x = lut[(q1.x & 255) << 5] * scale;
        o.y = lut[(q1.y & 255) << 5] * scale;
        o.z = lut[(q1.z & 255) << 5] * scale;
        o.w = lut[(q1.w & 255) << 5] * scale;
        orow[i + 256] = o;

        o.x = lut[(q2.x & 255) << 5] * scale;
        o.y = lut[(q2.y & 255) << 5] * scale;
        o.z = lut[(q2.z & 255) << 5] * scale;
        o.w = lut[(q2.w & 255) << 5] * scale;
        orow[i + 512] = o;

        o.x = lut[(q3.x & 255) << 5] * scale;
        o.y = lut[(q3.y & 255) << 5] * scale;
        o.z = lut[(q3.z & 255) << 5] * scale;
        o.w = lut[(q3.w & 255) << 5] * scale;
        orow[i + 768] = o;
    }
}

extern "C" void kernel_launch(void* const* d_in, const int* in_sizes, int n_in,
                              void* d_out, int out_size)
{
    const int*   input  = (const int*)  d_in[0];
    const int*   weight = (const int*)  d_in[1];
    const float* absmax = (const float*)d_in[2];
    const float* code   = (const float*)d_in[3];
    float*       out    = (float*)d_out;

    bnb_embed_kernel<<<NCTAS, THREADS>>>(input, weight, absmax, code, out);
}

// round 4
// speedup vs baseline: 1.1026x; 1.0466x over previous
#include <cuda_runtime.h>
#include <cstdint>

// FrozenBNBEmbedding: out[t, d] = code[ weight[input[t], d] ] * absmax[input[t]]
// DIM == BLOCK == 4096 -> absmax index == vocab row index.
//
// Inputs (metadata order):
//   d_in[0] = input  : int32 [4, 2048]       (8192 token ids)
//   d_in[1] = weight : int32 [50400, 4096]   (int8 codes as int32)
//   d_in[2] = absmax : float32 [50400]
//   d_in[3] = code   : float32 [256]
//   d_out   = float32 [4, 2048, 4096]
//
// Round-4: R1 skeleton (1 token per loop step, 256 thr, full occupancy)
// + 8-way bank-replicated LUT (8KB, conflict degree ~2 instead of ~4,
//   still 8 CTAs/SM)
// + persistent grid-stride over tokens (no wave tail, LUT init amortized)
// + streaming stores for the write-once output.

#define DIM      4096
#define NTOKENS  8192
#define THREADS  256
#define NSM      148
#define CTAS_PER_SM 8
#define NCTAS    (NSM * CTAS_PER_SM)   // 1184 persistent CTAs
#define LUT_REP  8

__global__ __launch_bounds__(THREADS, CTAS_PER_SM)
void bnb_embed_kernel(const int* __restrict__ input,
                      const int* __restrict__ weight,
                      const float* __restrict__ absmax,
                      const float* __restrict__ code,
                      float* __restrict__ out)
{
    // 8-way replicated LUT: word w holds code[w >> 3].
    // Lookup: s_lut[(byte << 3) + (lane & 7)].
    // Lane group c = lane&7 touches only banks {c, c+8, c+16, c+24}:
    // disjoint bank sets per group -> max conflict ~2 within 4-lane groups.
    __shared__ float s_lut[256 * LUT_REP];

    const int tid  = threadIdx.x;
    const int lane = tid & 31;

    #pragma unroll
    for (int w = tid; w < 256 * LUT_REP; w += THREADS)
        s_lut[w] = __ldg(&code[w >> 3]);   // coalesced STS, L1-hit LDG
    __syncthreads();

    const float* __restrict__ lut = s_lut + (lane & (LUT_REP - 1));

    // Persistent grid-stride over tokens.
    for (int t = blockIdx.x; t < NTOKENS; t += NCTAS) {
        const int tok = __ldg(&input[t]);
        const float scale = __ldg(&absmax[tok]);

        const int4* __restrict__ wrow =
            reinterpret_cast<const int4*>(weight + (size_t)tok * DIM);
        float4* __restrict__ orow =
            reinterpret_cast<float4*>(out + (size_t)t * DIM);

        // Front-batch all four 16B loads (MLP = 4 per thread).
        int4 q0 = wrow[tid];
        int4 q1 = wrow[tid + 256];
        int4 q2 = wrow[tid + 512];
        int4 q3 = wrow[tid + 768];

        float4 o;
        o.x = lut[(q0.x & 255) << 3] * scale;
        o.y = lut[(q0.y & 255) << 3] * scale;
        o.z = lut[(q0.z & 255) << 3] * scale;
        o.w = lut[(q0.w & 255) << 3] * scale;
        __stcs(&orow[tid], o);

        o.x = lut[(q1.x & 255) << 3] * scale;
        o.y = lut[(q1.y & 255) << 3] * scale;
        o.z = lut[(q1.z & 255) << 3] * scale;
        o.w = lut[(q1.w & 255) << 3] * scale;
        __stcs(&orow[tid + 256], o);

        o.x = lut[(q2.x & 255) << 3] * scale;
        o.y = lut[(q2.y & 255) << 3] * scale;
        o.z = lut[(q2.z & 255) << 3] * scale;
        o.w = lut[(q2.w & 255) << 3] * scale;
        __stcs(&orow[tid + 512], o);

        o.x = lut[(q3.x & 255) << 3] * scale;
        o.y = lut[(q3.y & 255) << 3] * scale;
        o.z = lut[(q3.z & 255) << 3] * scale;
        o.w = lut[(q3.w & 255) << 3] * scale;
        __stcs(&orow[tid + 768], o);
    }
}

extern "C" void kernel_launch(void* const* d_in, const int* in_sizes, int n_in,
                              void* d_out, int out_size)
{
    const int*   input  = (const int*)  d_in[0];
    const int*   weight = (const int*)  d_in[1];
    const float* absmax = (const float*)d_in[2];
    const float* code   = (const float*)d_in[3];
    float*       out    = (float*)d_out;

    bnb_embed_kernel<<<NCTAS, THREADS>>>(input, weight, absmax, code, out);
}